// round 1
// baseline (speedup 1.0000x reference)
#include <cuda_runtime.h>
#include <cuda_bf16.h>

// Scaled dot-product attention, B=1, H=16, S=4096, D=64, fp32.
// Flash-attention style: one CTA per (head, 64-query tile), 64-key tiles.
// Round 1 baseline: pure fp32 FFMA compute (numerically safe), SMEM-tiled,
// 4x4 register blocking, online softmax.

#define HEADS 16
#define SEQ   4096
#define DIM   64
#define BQ    64
#define BK    64
#define LD    68          // padded row stride (floats) for Q/K/V tiles
#define LDP   68          // padded row stride for P tile
#define NT    256
#define SCALE 0.125f      // 1/sqrt(64)

#define SMEM_FLOATS (4 * BQ * LD)
#define SMEM_BYTES  (SMEM_FLOATS * sizeof(float))

__global__ __launch_bounds__(NT, 2)
void fa_fp32_kernel(const float* __restrict__ Qg, const float* __restrict__ Kg,
                    const float* __restrict__ Vg, float* __restrict__ Og)
{
    extern __shared__ float smem[];
    float* sQ = smem;                 // [BQ][LD]
    float* sK = sQ + BQ * LD;         // [BK][LD]
    float* sV = sK + BK * LD;         // [BK][LD]
    float* sP = sV + BK * LD;         // [BQ][LDP]

    const int qt = blockIdx.x;        // query tile index (0..63)
    const int h  = blockIdx.y;        // head (0..15)
    const int t  = threadIdx.x;
    const int tx = t & 15;            // 0..15
    const int ty = t >> 4;            // 0..15
    const int i0 = ty * 4;            // this thread's 4 query rows

    const float* Qbase = Qg + ((size_t)h * SEQ + (size_t)qt * BQ) * DIM;
    const float* Kh    = Kg + (size_t)h * SEQ * DIM;
    const float* Vh    = Vg + (size_t)h * SEQ * DIM;

    // ---- load Q tile, prescaled by 1/sqrt(D) ----
    for (int idx = t; idx < BQ * (DIM / 4); idx += NT) {
        int r = idx >> 4;             // row 0..63
        int c = idx & 15;             // float4 col 0..15
        float4 v = ((const float4*)Qbase)[r * (DIM / 4) + c];
        v.x *= SCALE; v.y *= SCALE; v.z *= SCALE; v.w *= SCALE;
        *(float4*)&sQ[r * LD + c * 4] = v;
    }

    float o[4][4];
    float m_i[4], l_i[4];
    #pragma unroll
    for (int ii = 0; ii < 4; ii++) {
        m_i[ii] = -1e30f;
        l_i[ii] = 0.0f;
        #pragma unroll
        for (int jj = 0; jj < 4; jj++) o[ii][jj] = 0.0f;
    }

    for (int kt = 0; kt < SEQ / BK; kt++) {
        __syncthreads();   // prev iteration's PV reads of sV/sP done

        // ---- load K and V tiles ----
        const float* Kt = Kh + (size_t)kt * BK * DIM;
        const float* Vt = Vh + (size_t)kt * BK * DIM;
        for (int idx = t; idx < BK * (DIM / 4); idx += NT) {
            int r = idx >> 4;
            int c = idx & 15;
            *(float4*)&sK[r * LD + c * 4] = ((const float4*)Kt)[r * (DIM / 4) + c];
            *(float4*)&sV[r * LD + c * 4] = ((const float4*)Vt)[r * (DIM / 4) + c];
        }
        __syncthreads();

        // ---- S = Q K^T.  Thread owns rows i0..i0+3, cols {tx+16*jj} ----
        float s[4][4];
        #pragma unroll
        for (int ii = 0; ii < 4; ii++)
            #pragma unroll
            for (int jj = 0; jj < 4; jj++) s[ii][jj] = 0.0f;

        #pragma unroll
        for (int d = 0; d < DIM; d += 4) {
            float4 qa[4], kb[4];
            #pragma unroll
            for (int ii = 0; ii < 4; ii++)
                qa[ii] = *(const float4*)&sQ[(i0 + ii) * LD + d];
            #pragma unroll
            for (int jj = 0; jj < 4; jj++)
                kb[jj] = *(const float4*)&sK[(tx + jj * 16) * LD + d];
            #pragma unroll
            for (int ii = 0; ii < 4; ii++)
                #pragma unroll
                for (int jj = 0; jj < 4; jj++)
                    s[ii][jj] += qa[ii].x * kb[jj].x + qa[ii].y * kb[jj].y
                               + qa[ii].z * kb[jj].z + qa[ii].w * kb[jj].w;
        }

        // ---- online softmax per query row (reduce across the 16 tx lanes) ----
        #pragma unroll
        for (int ii = 0; ii < 4; ii++) {
            float tm = fmaxf(fmaxf(s[ii][0], s[ii][1]), fmaxf(s[ii][2], s[ii][3]));
            #pragma unroll
            for (int off = 8; off >= 1; off >>= 1)
                tm = fmaxf(tm, __shfl_xor_sync(0xffffffffu, tm, off));
            float mn = fmaxf(m_i[ii], tm);

            float p0 = __expf(s[ii][0] - mn);
            float p1 = __expf(s[ii][1] - mn);
            float p2 = __expf(s[ii][2] - mn);
            float p3 = __expf(s[ii][3] - mn);
            float sum = (p0 + p1) + (p2 + p3);
            #pragma unroll
            for (int off = 8; off >= 1; off >>= 1)
                sum += __shfl_xor_sync(0xffffffffu, sum, off);

            float corr = __expf(m_i[ii] - mn);
            m_i[ii] = mn;
            l_i[ii] = l_i[ii] * corr + sum;
            #pragma unroll
            for (int jj = 0; jj < 4; jj++) o[ii][jj] *= corr;

            sP[(i0 + ii) * LDP + tx]      = p0;
            sP[(i0 + ii) * LDP + tx + 16] = p1;
            sP[(i0 + ii) * LDP + tx + 32] = p2;
            sP[(i0 + ii) * LDP + tx + 48] = p3;
        }
        __syncthreads();

        // ---- O += P V.  Thread owns rows i0..i0+3, d-cols tx*4..tx*4+3 ----
        #pragma unroll
        for (int k = 0; k < BK; k += 4) {
            float4 pa[4], vb[4];
            #pragma unroll
            for (int ii = 0; ii < 4; ii++)
                pa[ii] = *(const float4*)&sP[(i0 + ii) * LDP + k];
            #pragma unroll
            for (int kk = 0; kk < 4; kk++)
                vb[kk] = *(const float4*)&sV[(k + kk) * LD + tx * 4];
            #pragma unroll
            for (int ii = 0; ii < 4; ii++) {
                o[ii][0] += pa[ii].x * vb[0].x + pa[ii].y * vb[1].x
                          + pa[ii].z * vb[2].x + pa[ii].w * vb[3].x;
                o[ii][1] += pa[ii].x * vb[0].y + pa[ii].y * vb[1].y
                          + pa[ii].z * vb[2].y + pa[ii].w * vb[3].y;
                o[ii][2] += pa[ii].x * vb[0].z + pa[ii].y * vb[1].z
                          + pa[ii].z * vb[2].z + pa[ii].w * vb[3].z;
                o[ii][3] += pa[ii].x * vb[0].w + pa[ii].y * vb[1].w
                          + pa[ii].z * vb[2].w + pa[ii].w * vb[3].w;
            }
        }
    }

    // ---- epilogue: normalize and store ----
    #pragma unroll
    for (int ii = 0; ii < 4; ii++) {
        float inv = 1.0f / l_i[ii];
        float4 r;
        r.x = o[ii][0] * inv;
        r.y = o[ii][1] * inv;
        r.z = o[ii][2] * inv;
        r.w = o[ii][3] * inv;
        size_t q = (size_t)qt * BQ + i0 + ii;
        size_t off = (((size_t)h * SEQ + q) * DIM + (size_t)tx * 4);
        *(float4*)&Og[off] = r;
    }
}

extern "C" void kernel_launch(void* const* d_in, const int* in_sizes, int n_in,
                              void* d_out, int out_size)
{
    const float* Q = (const float*)d_in[0];
    const float* K = (const float*)d_in[1];
    const float* V = (const float*)d_in[2];
    float* O = (float*)d_out;

    cudaFuncSetAttribute(fa_fp32_kernel,
                         cudaFuncAttributeMaxDynamicSharedMemorySize,
                         (int)SMEM_BYTES);

    dim3 grid(SEQ / BQ, HEADS, 1);   // 64 x 16 = 1024 CTAs
    fa_fp32_kernel<<<grid, NT, SMEM_BYTES>>>(Q, K, V, O);
}